// round 14
// baseline (speedup 1.0000x reference)
#include <cuda_runtime.h>
#include <cstdint>

#define N_   16
#define T_   32
#define D_   768
#define DH   (D_ / 2)       // 384 per d-half
#define L_   196
#define NLB  7
#define DC   4
#define NCH  (DH / DC)      // 96 chunks per d-half (scores)
#define NBUF 4              // lookahead 2 + 1 live + 1 kept for kt epilogue

typedef unsigned long long u64;

// raw partial scores per d-half
__device__ float g_part[2][N_ * T_ * T_ * L_];
// transposed k: kt[n][s][l][d]  (written by scores_kernel epilogue)
__device__ float g_kt[N_ * T_ * L_ * D_];
// softmaxed attn, duplicated f32x2: g_a2[n][s*32+t][l]
__device__ u64 g_a2[N_ * T_ * T_ * L_];

extern __shared__ float smem_[];
#define A_SMEM_BYTES (NBUF * DC * 32 * 32 * 4)   // 65536
#define SK(b, dd, s, l) ((((b) * DC + (dd)) * 32 + (s)) * 32 + (l))

// ---- packed f32x2 helpers ----
__device__ __forceinline__ u64 pack2(float x, float y) {
    u64 r; asm("mov.b64 %0, {%1, %2};" : "=l"(r) : "f"(x), "f"(y)); return r;
}
__device__ __forceinline__ void unpack2(u64 v, float& x, float& y) {
    asm("mov.b64 {%0, %1}, %2;" : "=f"(x), "=f"(y) : "l"(v));
}
__device__ __forceinline__ u64 fma2_(u64 a, u64 b, u64 c) {
    u64 r; asm("fma.rn.f32x2 %0, %1, %2, %3;" : "=l"(r) : "l"(a), "l"(b), "l"(c)); return r;
}
__device__ __forceinline__ u64 add2_(u64 a, u64 b) {
    u64 r; asm("add.rn.f32x2 %0, %1, %2;" : "=l"(r) : "l"(a), "l"(b)); return r;
}

// ---- cp.async ----
__device__ __forceinline__ void cp16(uint32_t dst, const float* src) {
    asm volatile("cp.async.ca.shared.global [%0], [%1], 16;" :: "r"(dst), "l"(src));
}
__device__ __forceinline__ void cp_commit() { asm volatile("cp.async.commit_group;"); }
__device__ __forceinline__ void cp_wait1()  { asm volatile("cp.async.wait_group 1;"); }
__device__ __forceinline__ void cp_wait0()  { asm volatile("cp.async.wait_group 0;"); }

// =====================================================================
// Kernel A: partial scores over one d-half + kt write-out.
// Grid (14, 16, 2): x = 2*lblock + tz (tz-partners adjacent -> k L2
// reuse), z = dz. Block 128, warp = 4 t's, lanes = l.
// tz=0 CTAs additionally write g_kt from the staged smem every odd
// chunk (pairs of DC=4 chunks -> full 32B sectors, no amplification).
// NBUF=4 keeps chunk c-1 alive through iteration c for the epilogue.
// =====================================================================
__global__ __launch_bounds__(128, 3)
void scores_kernel(const float* __restrict__ q, const float* __restrict__ k,
                   const float* __restrict__ peq)
{
    const int tid  = threadIdx.x;
    const int lane = tid & 31;
    const int tg   = tid >> 5;
    const int l0   = (blockIdx.x >> 1) * 32;
    const int tz   = blockIdx.x & 1;
    const int n    = blockIdx.y;
    const int dz   = blockIdx.z;
    const int t0   = tz * 16 + tg * 4;
    const int l    = l0 + lane;
    const bool lv  = (l < L_);
    const int dbase = dz * DH;

    for (int i = tid; i < NBUF * DC * 32 * 32; i += 128) smem_[i] = 0.f;
    __syncthreads();

    const uint32_t sbase = (uint32_t)__cvta_generic_to_shared(smem_);

    const int ll  = (tid & 7) * 4;
    const bool kv_ok = (l0 + ll < L_);
    const float* kb0 = k + ((size_t)n * T_ * D_ + dbase) * L_ + l0 + ll;

    auto issue = [&](int c, int buf) {
        const size_t cL = (size_t)(c * DC) * L_;
        if (kv_ok) {
#pragma unroll
            for (int i = 0; i < 8; i++) {
                int r  = i * 16 + (tid >> 3);
                int s  = r & 31;
                int dd = r >> 5;
                cp16(sbase + (uint32_t)SK(buf, dd, s, ll) * 4,
                     kb0 + ((size_t)s * D_ + dd) * L_ + cL);
            }
        }
        cp_commit();
    };

    const float* qb0 = q + ((size_t)n * T_ * D_ + dbase) * L_ + l;
    const float* pb0 = peq + (size_t)l * D_ + dbase;

    auto loadq = [&](int c, float (&qr)[4][DC]) {
        if (lv) {
            float4 e = *reinterpret_cast<const float4*>(pb0 + c * DC);
            const size_t cL = (size_t)(c * DC) * L_;
#pragma unroll
            for (int i = 0; i < 4; i++) {
                qr[i][0] = __ldg(qb0 + ((size_t)(t0 + i) * D_ + 0) * L_ + cL) + e.x;
                qr[i][1] = __ldg(qb0 + ((size_t)(t0 + i) * D_ + 1) * L_ + cL) + e.y;
                qr[i][2] = __ldg(qb0 + ((size_t)(t0 + i) * D_ + 2) * L_ + cL) + e.z;
                qr[i][3] = __ldg(qb0 + ((size_t)(t0 + i) * D_ + 3) * L_ + cL) + e.w;
            }
        } else {
#pragma unroll
            for (int i = 0; i < 4; i++)
#pragma unroll
                for (int dd = 0; dd < DC; dd++) qr[i][dd] = 0.f;
        }
    };

    u64 acc[4][16];
#pragma unroll
    for (int i = 0; i < 4; i++)
#pragma unroll
        for (int sp = 0; sp < 16; sp++) acc[i][sp] = 0ULL;

    float qc[4][DC], qn[4][DC];
    issue(0, 0);
    issue(1, 1);
    loadq(0, qc);

    for (int c = 0; c < NCH; ++c) {
        if (c + 1 < NCH) cp_wait1(); else cp_wait0();
        __syncthreads();
        if (c + 2 < NCH) issue(c + 2, (c + 2) % NBUF);
        if (c + 1 < NCH) loadq(c + 1, qn);

        const int buf = c % NBUF;
#pragma unroll
        for (int dd = 0; dd < DC; dd++) {
            u64 qv0 = pack2(qc[0][dd], qc[0][dd]);
            u64 qv1 = pack2(qc[1][dd], qc[1][dd]);
            u64 qv2 = pack2(qc[2][dd], qc[2][dd]);
            u64 qv3 = pack2(qc[3][dd], qc[3][dd]);
            const float* kb = &smem_[SK(buf, dd, 0, lane)];
#pragma unroll
            for (int sp = 0; sp < 16; sp++) {
                u64 kv = pack2(kb[(2 * sp) * 32], kb[(2 * sp + 1) * 32]);
                acc[0][sp] = fma2_(qv0, kv, acc[0][sp]);
                acc[1][sp] = fma2_(qv1, kv, acc[1][sp]);
                acc[2][sp] = fma2_(qv2, kv, acc[2][sp]);
                acc[3][sp] = fma2_(qv3, kv, acc[3][sp]);
            }
        }

        // ---- kt write-out epilogue: every odd chunk, tz=0 CTAs only.
        // Buffers (c-1)%4 and c%4 hold chunks c-1, c (NBUF=4 keeps c-1
        // alive: the overwrite of (c-1)%4 = issue(c+3) happens after the
        // iter-c+1 barrier). Two adjacent float4 stores per (s,l) = one
        // full 32B sector of kt -> no write amplification.
        if (tz == 0 && (c & 1) && lv) {
            const int b0 = (c - 1) % NBUF;
            const int b1 = c % NBUF;
            const int dq = dbase + (c - 1) * DC;
#pragma unroll
            for (int j = 0; j < 8; j++) {
                const int s = tg * 8 + j;
                float4 v0 = make_float4(smem_[SK(b0, 0, s, lane)],
                                        smem_[SK(b0, 1, s, lane)],
                                        smem_[SK(b0, 2, s, lane)],
                                        smem_[SK(b0, 3, s, lane)]);
                float4 v1 = make_float4(smem_[SK(b1, 0, s, lane)],
                                        smem_[SK(b1, 1, s, lane)],
                                        smem_[SK(b1, 2, s, lane)],
                                        smem_[SK(b1, 3, s, lane)]);
                float* kp = g_kt + (((size_t)n * T_ + s) * L_ + l) * D_ + dq;
                *reinterpret_cast<float4*>(kp)     = v0;
                *reinterpret_cast<float4*>(kp + 4) = v1;
            }
        }

#pragma unroll
        for (int i = 0; i < 4; i++)
#pragma unroll
            for (int dd = 0; dd < DC; dd++) qc[i][dd] = qn[i][dd];
    }

    if (lv) {
#pragma unroll
        for (int i = 0; i < 4; i++) {
            float* ap = &g_part[dz][(((size_t)n * T_ + t0 + i) * T_) * L_ + l];
#pragma unroll
            for (int sp = 0; sp < 16; sp++) {
                float x, y;
                unpack2(acc[i][sp], x, y);
                ap[(2 * sp) * L_]     = x;
                ap[(2 * sp + 1) * L_] = y;
            }
        }
    }
}

// =====================================================================
// Reduce + softmax -> duplicated f32x2 attn table.
// =====================================================================
__global__ __launch_bounds__(256)
void reduce_softmax_kernel()
{
    const int idx = blockIdx.x * 256 + threadIdx.x;
    if (idx >= N_ * T_ * L_) return;
    const int l = idx % L_;
    const int t = (idx / L_) % T_;
    const int n = idx / (T_ * L_);

    const size_t base = (((size_t)n * T_ + t) * T_) * L_ + l;
    const float scale = 0.03608439182435161f;

    float v[32];
    float m = -1e30f;
#pragma unroll
    for (int s = 0; s < 32; s++) {
        v[s] = (g_part[0][base + s * L_] + g_part[1][base + s * L_]) * scale;
        m = fmaxf(m, v[s]);
    }
    float sum = 0.f;
#pragma unroll
    for (int s = 0; s < 32; s++) { float e = __expf(v[s] - m); v[s] = e; sum += e; }
    const float inv = 1.f / sum;
#pragma unroll
    for (int s = 0; s < 32; s++) {
        float a = v[s] * inv;
        g_a2[((size_t)n * 1024 + s * 32 + t) * L_ + l] = pack2(a, a);
    }
}

// =====================================================================
// Kernel B v4 (unchanged from R13): out = sum_s a*kt + pek, MLP-4 ring.
// Grid (98, 16): x = 2*lblock + dz. Block 128 = 4 warps, warp = l;
// lanes = d-pairs. No barriers in the mainloop.
// =====================================================================
__global__ __launch_bounds__(128, 4)
void out_kernel(const float* __restrict__ pek, float* __restrict__ out)
{
    __shared__ u64 sa[4 * 1024];   // [l-idx][s*32+t]

    const int tid  = threadIdx.x;
    const int lane = tid & 31;
    const int w    = tid >> 5;
    const int l0   = (blockIdx.x >> 1) * 4;   // 196 = 49*4
    const int dz   = blockIdx.x & 1;
    const int n    = blockIdx.y;

    // prologue: a tile for 4 l's
#pragma unroll
    for (int i = 0; i < 32; i++) {
        int flat = i * 128 + tid;
        int st = flat >> 2;
        int li = flat & 3;
        sa[li * 1024 + st] = g_a2[((size_t)n * 1024 + st) * L_ + l0 + li];
    }
    __syncthreads();

    const int l = l0 + w;
    const u64* sa_w = sa + w * 1024;
    const float* ktb = g_kt + (((size_t)n * T_) * L_ + l) * D_;
    const int SSTRIDE = L_ * D_ / 2;          // u64 stride between s

    for (int dc = 0; dc < 6; dc++) {
        const int d0 = dz * DH + dc * 64 + 2 * lane;
        const u64* kp = reinterpret_cast<const u64*>(ktb + d0);

        u64 oc[32];
#pragma unroll
        for (int t = 0; t < 32; t++) oc[t] = 0ULL;

        // 4-deep prefetch ring: 4 LDGs in flight per warp at all times
        u64 kvb[4];
#pragma unroll
        for (int j = 0; j < 4; j++) kvb[j] = __ldg(kp + (size_t)j * SSTRIDE);

#pragma unroll
        for (int s = 0; s < 32; s++) {
            u64 kvc = kvb[s & 3];
            if (s + 4 < 32) kvb[s & 3] = __ldg(kp + (size_t)(s + 4) * SSTRIDE);
            const ulonglong2* ap = reinterpret_cast<const ulonglong2*>(sa_w + s * 32);
#pragma unroll
            for (int tp = 0; tp < 16; tp++) {
                ulonglong2 a = ap[tp];
                oc[2 * tp]     = fma2_(a.x, kvc, oc[2 * tp]);
                oc[2 * tp + 1] = fma2_(a.y, kvc, oc[2 * tp + 1]);
            }
        }

        const u64 pe = *reinterpret_cast<const u64*>(pek + (size_t)l * D_ + d0);
#pragma unroll
        for (int t = 0; t < 32; t++) {
            *reinterpret_cast<u64*>(
                out + (((size_t)n * T_ + t) * L_ + l) * D_ + d0) = add2_(oc[t], pe);
        }
    }
}

extern "C" void kernel_launch(void* const* d_in, const int* in_sizes, int n_in,
                              void* d_out, int out_size)
{
    const float* q   = (const float*)d_in[0];
    const float* k   = (const float*)d_in[1];
    const float* peq = (const float*)d_in[2];
    const float* pek = (const float*)d_in[3];
    float* out = (float*)d_out;

    static int configured = 0;
    if (!configured) {
        cudaFuncSetAttribute(scores_kernel,
                             cudaFuncAttributeMaxDynamicSharedMemorySize, A_SMEM_BYTES);
        configured = 1;
    }

    scores_kernel<<<dim3(2 * NLB, N_, 2), 128, A_SMEM_BYTES>>>(q, k, peq);
    reduce_softmax_kernel<<<(N_ * T_ * L_ + 255) / 256, 256>>>();
    out_kernel<<<dim3(98, N_), 128>>>(pek, out);
}

// round 15
// speedup vs baseline: 1.2040x; 1.2040x over previous
#include <cuda_runtime.h>
#include <cstdint>

#define N_   16
#define T_   32
#define D_   768
#define DH   (D_ / 2)       // 384 per d-half
#define L_   196
#define NLB  7
#define DC   6
#define NCH  (DH / DC)      // 64 chunks per d-half (scores)
#define NBUF 3

typedef unsigned long long u64;

// raw partial scores per d-half
__device__ float g_part[2][N_ * T_ * T_ * L_];
// transposed k: kt[n][s][l][d]
__device__ float g_kt[N_ * T_ * L_ * D_];
// softmaxed attn, duplicated f32x2: g_a2[n][s*32+t][l]
__device__ u64 g_a2[N_ * T_ * T_ * L_];

extern __shared__ float smem_[];
#define A_SMEM_BYTES (NBUF * DC * 32 * 32 * 4)   // 73728
#define SK(b, dd, s, l) ((((b) * DC + (dd)) * 32 + (s)) * 32 + (l))

// ---- packed f32x2 helpers ----
__device__ __forceinline__ u64 pack2(float x, float y) {
    u64 r; asm("mov.b64 %0, {%1, %2};" : "=l"(r) : "f"(x), "f"(y)); return r;
}
__device__ __forceinline__ void unpack2(u64 v, float& x, float& y) {
    asm("mov.b64 {%0, %1}, %2;" : "=f"(x), "=f"(y) : "l"(v));
}
__device__ __forceinline__ u64 fma2_(u64 a, u64 b, u64 c) {
    u64 r; asm("fma.rn.f32x2 %0, %1, %2, %3;" : "=l"(r) : "l"(a), "l"(b), "l"(c)); return r;
}
__device__ __forceinline__ u64 add2_(u64 a, u64 b) {
    u64 r; asm("add.rn.f32x2 %0, %1, %2;" : "=l"(r) : "l"(a), "l"(b)); return r;
}

// ---- cp.async ----
__device__ __forceinline__ void cp16(uint32_t dst, const float* src) {
    asm volatile("cp.async.ca.shared.global [%0], [%1], 16;" :: "r"(dst), "l"(src));
}
__device__ __forceinline__ void cp_commit() { asm volatile("cp.async.commit_group;"); }
__device__ __forceinline__ void cp_wait1()  { asm volatile("cp.async.wait_group 1;"); }
__device__ __forceinline__ void cp_wait0()  { asm volatile("cp.async.wait_group 0;"); }

// =====================================================================
// Transpose: g_kt[n][s][l][d] = k[n][s][d][l]. Coalesced both ways.
// =====================================================================
__global__ __launch_bounds__(256)
void transpose_kernel(const float* __restrict__ k)
{
    __shared__ float tile[32][33];
    const int ns = blockIdx.z;
    const int l0 = blockIdx.y * 32;
    const int tid = threadIdx.x;
    const int c  = tid & 31;
    const int r0 = tid >> 5;
    const size_t base = (size_t)ns * D_ * L_;

    for (int j = 0; j < 4; j++) {
        const int d0 = (blockIdx.x * 4 + j) * 32;
#pragma unroll
        for (int rr = r0; rr < 32; rr += 8)
            tile[rr][c] = (l0 + c < L_) ? k[base + (size_t)(d0 + rr) * L_ + l0 + c] : 0.f;
        __syncthreads();
#pragma unroll
        for (int rr = r0; rr < 32; rr += 8)
            if (l0 + rr < L_)
                g_kt[base + (size_t)(l0 + rr) * D_ + d0 + c] = tile[c][rr];
        __syncthreads();
    }
}

// =====================================================================
// Kernel A: partial scores over one d-half. DC=6: 64 chunks/barriers.
// Grid (14, 16, 2): x = 2*lblock + tz (tz-partners adjacent -> k L2
// reuse), z = dz. Block 128, warp = 4 t's, lanes = l.
// q DOUBLE-BUFFERED (loadq(c+1) after the barrier, consumed next iter)
// -- the R11 regression came from collapsing this prefetch distance.
// =====================================================================
__global__ __launch_bounds__(128, 3)
void scores_kernel(const float* __restrict__ q, const float* __restrict__ k,
                   const float* __restrict__ peq)
{
    const int tid  = threadIdx.x;
    const int lane = tid & 31;
    const int tg   = tid >> 5;
    const int l0   = (blockIdx.x >> 1) * 32;
    const int tz   = blockIdx.x & 1;
    const int n    = blockIdx.y;
    const int dz   = blockIdx.z;
    const int t0   = tz * 16 + tg * 4;
    const int l    = l0 + lane;
    const bool lv  = (l < L_);
    const int dbase = dz * DH;

    for (int i = tid; i < NBUF * DC * 32 * 32; i += 128) smem_[i] = 0.f;
    __syncthreads();

    const uint32_t sbase = (uint32_t)__cvta_generic_to_shared(smem_);

    const int ll  = (tid & 7) * 4;
    const bool kv_ok = (l0 + ll < L_);
    const float* kb0 = k + ((size_t)n * T_ * D_ + dbase) * L_ + l0 + ll;

    auto issue = [&](int c, int buf) {
        const size_t cL = (size_t)(c * DC) * L_;
        if (kv_ok) {
#pragma unroll
            for (int i = 0; i < 12; i++) {
                int r  = i * 16 + (tid >> 3);  // 0..191
                int s  = r & 31;
                int dd = r >> 5;               // 0..5
                cp16(sbase + (uint32_t)SK(buf, dd, s, ll) * 4,
                     kb0 + ((size_t)s * D_ + dd) * L_ + cL);
            }
        }
        cp_commit();
    };

    const float* qb0 = q + ((size_t)n * T_ * D_ + dbase) * L_ + l;
    const float* pb0 = peq + (size_t)l * D_ + dbase;

    auto loadq = [&](int c, float (&qr)[4][DC]) {
        if (lv) {
            const float* pe = pb0 + c * DC;
            float2 e0 = *reinterpret_cast<const float2*>(pe);
            float2 e1 = *reinterpret_cast<const float2*>(pe + 2);
            float2 e2 = *reinterpret_cast<const float2*>(pe + 4);
            float e[6] = {e0.x, e0.y, e1.x, e1.y, e2.x, e2.y};
            const size_t cL = (size_t)(c * DC) * L_;
#pragma unroll
            for (int i = 0; i < 4; i++)
#pragma unroll
                for (int dd = 0; dd < DC; dd++)
                    qr[i][dd] = __ldg(qb0 + ((size_t)(t0 + i) * D_ + dd) * L_ + cL) + e[dd];
        } else {
#pragma unroll
            for (int i = 0; i < 4; i++)
#pragma unroll
                for (int dd = 0; dd < DC; dd++) qr[i][dd] = 0.f;
        }
    };

    u64 acc[4][16];
#pragma unroll
    for (int i = 0; i < 4; i++)
#pragma unroll
        for (int sp = 0; sp < 16; sp++) acc[i][sp] = 0ULL;

    float qc[4][DC], qn[4][DC];
    issue(0, 0);
    issue(1, 1);
    loadq(0, qc);

    for (int c = 0; c < NCH; ++c) {
        if (c + 1 < NCH) cp_wait1(); else cp_wait0();
        __syncthreads();
        if (c + 2 < NCH) issue(c + 2, (c + 2) % NBUF);
        if (c + 1 < NCH) loadq(c + 1, qn);

        const int buf = c % NBUF;
#pragma unroll
        for (int dd = 0; dd < DC; dd++) {
            u64 qv0 = pack2(qc[0][dd], qc[0][dd]);
            u64 qv1 = pack2(qc[1][dd], qc[1][dd]);
            u64 qv2 = pack2(qc[2][dd], qc[2][dd]);
            u64 qv3 = pack2(qc[3][dd], qc[3][dd]);
            const float* kb = &smem_[SK(buf, dd, 0, lane)];
#pragma unroll
            for (int sp = 0; sp < 16; sp++) {
                u64 kv = pack2(kb[(2 * sp) * 32], kb[(2 * sp + 1) * 32]);
                acc[0][sp] = fma2_(qv0, kv, acc[0][sp]);
                acc[1][sp] = fma2_(qv1, kv, acc[1][sp]);
                acc[2][sp] = fma2_(qv2, kv, acc[2][sp]);
                acc[3][sp] = fma2_(qv3, kv, acc[3][sp]);
            }
        }
#pragma unroll
        for (int i = 0; i < 4; i++)
#pragma unroll
            for (int dd = 0; dd < DC; dd++) qc[i][dd] = qn[i][dd];
    }

    if (lv) {
#pragma unroll
        for (int i = 0; i < 4; i++) {
            float* ap = &g_part[dz][(((size_t)n * T_ + t0 + i) * T_) * L_ + l];
#pragma unroll
            for (int sp = 0; sp < 16; sp++) {
                float x, y;
                unpack2(acc[i][sp], x, y);
                ap[(2 * sp) * L_]     = x;
                ap[(2 * sp + 1) * L_] = y;
            }
        }
    }
}

// =====================================================================
// Reduce + softmax -> duplicated f32x2 attn table.
// =====================================================================
__global__ __launch_bounds__(256)
void reduce_softmax_kernel()
{
    const int idx = blockIdx.x * 256 + threadIdx.x;
    if (idx >= N_ * T_ * L_) return;
    const int l = idx % L_;
    const int t = (idx / L_) % T_;
    const int n = idx / (T_ * L_);

    const size_t base = (((size_t)n * T_ + t) * T_) * L_ + l;
    const float scale = 0.03608439182435161f;

    float v[32];
    float m = -1e30f;
#pragma unroll
    for (int s = 0; s < 32; s++) {
        v[s] = (g_part[0][base + s * L_] + g_part[1][base + s * L_]) * scale;
        m = fmaxf(m, v[s]);
    }
    float sum = 0.f;
#pragma unroll
    for (int s = 0; s < 32; s++) { float e = __expf(v[s] - m); v[s] = e; sum += e; }
    const float inv = 1.f / sum;
#pragma unroll
    for (int s = 0; s < 32; s++) {
        float a = v[s] * inv;
        g_a2[((size_t)n * 1024 + s * 32 + t) * L_ + l] = pack2(a, a);
    }
}

// =====================================================================
// Kernel B v4 (R13, unchanged): out = sum_s a*kt + pek, MLP-4 ring.
// Grid (98, 16): x = 2*lblock + dz. Block 128 = 4 warps, warp = l;
// lanes = d-pairs. No barriers in the mainloop.
// =====================================================================
__global__ __launch_bounds__(128, 4)
void out_kernel(const float* __restrict__ pek, float* __restrict__ out)
{
    __shared__ u64 sa[4 * 1024];   // [l-idx][s*32+t]

    const int tid  = threadIdx.x;
    const int lane = tid & 31;
    const int w    = tid >> 5;
    const int l0   = (blockIdx.x >> 1) * 4;   // 196 = 49*4
    const int dz   = blockIdx.x & 1;
    const int n    = blockIdx.y;

    // prologue: a tile for 4 l's
#pragma unroll
    for (int i = 0; i < 32; i++) {
        int flat = i * 128 + tid;
        int st = flat >> 2;
        int li = flat & 3;
        sa[li * 1024 + st] = g_a2[((size_t)n * 1024 + st) * L_ + l0 + li];
    }
    __syncthreads();

    const int l = l0 + w;
    const u64* sa_w = sa + w * 1024;
    const float* ktb = g_kt + (((size_t)n * T_) * L_ + l) * D_;
    const int SSTRIDE = L_ * D_ / 2;          // u64 stride between s

    for (int dc = 0; dc < 6; dc++) {
        const int d0 = dz * DH + dc * 64 + 2 * lane;
        const u64* kp = reinterpret_cast<const u64*>(ktb + d0);

        u64 oc[32];
#pragma unroll
        for (int t = 0; t < 32; t++) oc[t] = 0ULL;

        // 4-deep prefetch ring: 4 LDGs in flight per warp at all times
        u64 kvb[4];
#pragma unroll
        for (int j = 0; j < 4; j++) kvb[j] = __ldg(kp + (size_t)j * SSTRIDE);

#pragma unroll
        for (int s = 0; s < 32; s++) {
            u64 kvc = kvb[s & 3];
            if (s + 4 < 32) kvb[s & 3] = __ldg(kp + (size_t)(s + 4) * SSTRIDE);
            const ulonglong2* ap = reinterpret_cast<const ulonglong2*>(sa_w + s * 32);
#pragma unroll
            for (int tp = 0; tp < 16; tp++) {
                ulonglong2 a = ap[tp];
                oc[2 * tp]     = fma2_(a.x, kvc, oc[2 * tp]);
                oc[2 * tp + 1] = fma2_(a.y, kvc, oc[2 * tp + 1]);
            }
        }

        const u64 pe = *reinterpret_cast<const u64*>(pek + (size_t)l * D_ + d0);
#pragma unroll
        for (int t = 0; t < 32; t++) {
            *reinterpret_cast<u64*>(
                out + (((size_t)n * T_ + t) * L_ + l) * D_ + d0) = add2_(oc[t], pe);
        }
    }
}

extern "C" void kernel_launch(void* const* d_in, const int* in_sizes, int n_in,
                              void* d_out, int out_size)
{
    const float* q   = (const float*)d_in[0];
    const float* k   = (const float*)d_in[1];
    const float* peq = (const float*)d_in[2];
    const float* pek = (const float*)d_in[3];
    float* out = (float*)d_out;

    static int configured = 0;
    if (!configured) {
        cudaFuncSetAttribute(scores_kernel,
                             cudaFuncAttributeMaxDynamicSharedMemorySize, A_SMEM_BYTES);
        configured = 1;
    }

    transpose_kernel<<<dim3(6, 7, N_ * T_), 256>>>(k);
    scores_kernel<<<dim3(2 * NLB, N_, 2), 128, A_SMEM_BYTES>>>(q, k, peq);
    reduce_softmax_kernel<<<(N_ * T_ * L_ + 255) / 256, 256>>>();
    out_kernel<<<dim3(98, N_), 128>>>(pek, out);
}

// round 16
// speedup vs baseline: 1.4791x; 1.2284x over previous
#include <cuda_runtime.h>
#include <cstdint>

#define N_   16
#define T_   32
#define D_   768
#define DH   (D_ / 2)       // 384 per d-half
#define L_   196
#define NLB  7
#define DC   4
#define NCH  (DH / DC)      // 96 chunks per d-half (scores)
#define NBUF 3

typedef unsigned long long u64;

// raw partial scores per d-half
__device__ float g_part[2][N_ * T_ * T_ * L_];
// transposed k: kt[n][s][l][d]
__device__ float g_kt[N_ * T_ * L_ * D_];
// softmaxed attn, duplicated f32x2: g_a2[n][s*32+t][l]
__device__ u64 g_a2[N_ * T_ * T_ * L_];

// ---- packed f32x2 helpers ----
__device__ __forceinline__ u64 pack2(float x, float y) {
    u64 r; asm("mov.b64 %0, {%1, %2};" : "=l"(r) : "f"(x), "f"(y)); return r;
}
__device__ __forceinline__ void unpack2(u64 v, float& x, float& y) {
    asm("mov.b64 {%0, %1}, %2;" : "=f"(x), "=f"(y) : "l"(v));
}
__device__ __forceinline__ u64 fma2_(u64 a, u64 b, u64 c) {
    u64 r; asm("fma.rn.f32x2 %0, %1, %2, %3;" : "=l"(r) : "l"(a), "l"(b), "l"(c)); return r;
}
__device__ __forceinline__ u64 add2_(u64 a, u64 b) {
    u64 r; asm("add.rn.f32x2 %0, %1, %2;" : "=l"(r) : "l"(a), "l"(b)); return r;
}

// ---- cp.async ----
__device__ __forceinline__ void cp16(uint32_t dst, const float* src) {
    asm volatile("cp.async.ca.shared.global [%0], [%1], 16;" :: "r"(dst), "l"(src));
}
__device__ __forceinline__ void cp_commit() { asm volatile("cp.async.commit_group;"); }
__device__ __forceinline__ void cp_wait1()  { asm volatile("cp.async.wait_group 1;"); }
__device__ __forceinline__ void cp_wait0()  { asm volatile("cp.async.wait_group 0;"); }

#define SK(b, dd, s, l) ((((b) * DC + (dd)) * 32 + (s)) * 32 + (l))

// =====================================================================
// Transpose: g_kt[n][s][l][d] = k[n][s][d][l]. Coalesced both ways.
// =====================================================================
__global__ __launch_bounds__(256)
void transpose_kernel(const float* __restrict__ k)
{
    __shared__ float tile[32][33];
    const int ns = blockIdx.z;
    const int l0 = blockIdx.y * 32;
    const int tid = threadIdx.x;
    const int c  = tid & 31;
    const int r0 = tid >> 5;
    const size_t base = (size_t)ns * D_ * L_;

    for (int j = 0; j < 4; j++) {
        const int d0 = (blockIdx.x * 4 + j) * 32;
#pragma unroll
        for (int rr = r0; rr < 32; rr += 8)
            tile[rr][c] = (l0 + c < L_) ? k[base + (size_t)(d0 + rr) * L_ + l0 + c] : 0.f;
        __syncthreads();
#pragma unroll
        for (int rr = r0; rr < 32; rr += 8)
            if (l0 + rr < L_)
                g_kt[base + (size_t)(l0 + rr) * D_ + d0 + c] = tile[c][rr];
        __syncthreads();
    }
}

// =====================================================================
// Kernel A (R13 exact): partial scores over one d-half, DC=4.
// Grid (14, 16, 2): x = 2*lblock + tz, z = dz. Block 128, warp = 4 t's.
// =====================================================================
__global__ __launch_bounds__(128, 3)
void scores_kernel(const float* __restrict__ q, const float* __restrict__ k,
                   const float* __restrict__ peq)
{
    __shared__ float sk[NBUF * DC * 32 * 32];

    const int tid  = threadIdx.x;
    const int lane = tid & 31;
    const int tg   = tid >> 5;
    const int l0   = (blockIdx.x >> 1) * 32;
    const int tz   = blockIdx.x & 1;
    const int n    = blockIdx.y;
    const int dz   = blockIdx.z;
    const int t0   = tz * 16 + tg * 4;
    const int l    = l0 + lane;
    const bool lv  = (l < L_);
    const int dbase = dz * DH;

    for (int i = tid; i < NBUF * DC * 32 * 32; i += 128) sk[i] = 0.f;
    __syncthreads();

    const uint32_t sbase = (uint32_t)__cvta_generic_to_shared(sk);

    const int ll  = (tid & 7) * 4;
    const bool kv_ok = (l0 + ll < L_);
    const float* kb0 = k + ((size_t)n * T_ * D_ + dbase) * L_ + l0 + ll;

    auto issue = [&](int c, int buf) {
        const size_t cL = (size_t)(c * DC) * L_;
        if (kv_ok) {
#pragma unroll
            for (int i = 0; i < 8; i++) {
                int r  = i * 16 + (tid >> 3);
                int s  = r & 31;
                int dd = r >> 5;
                cp16(sbase + (uint32_t)SK(buf, dd, s, ll) * 4,
                     kb0 + ((size_t)s * D_ + dd) * L_ + cL);
            }
        }
        cp_commit();
    };

    const float* qb0 = q + ((size_t)n * T_ * D_ + dbase) * L_ + l;
    const float* pb0 = peq + (size_t)l * D_ + dbase;

    auto loadq = [&](int c, float (&qr)[4][DC]) {
        if (lv) {
            float4 e = *reinterpret_cast<const float4*>(pb0 + c * DC);
            const size_t cL = (size_t)(c * DC) * L_;
#pragma unroll
            for (int i = 0; i < 4; i++) {
                qr[i][0] = __ldg(qb0 + ((size_t)(t0 + i) * D_ + 0) * L_ + cL) + e.x;
                qr[i][1] = __ldg(qb0 + ((size_t)(t0 + i) * D_ + 1) * L_ + cL) + e.y;
                qr[i][2] = __ldg(qb0 + ((size_t)(t0 + i) * D_ + 2) * L_ + cL) + e.z;
                qr[i][3] = __ldg(qb0 + ((size_t)(t0 + i) * D_ + 3) * L_ + cL) + e.w;
            }
        } else {
#pragma unroll
            for (int i = 0; i < 4; i++)
#pragma unroll
                for (int dd = 0; dd < DC; dd++) qr[i][dd] = 0.f;
        }
    };

    u64 acc[4][16];
#pragma unroll
    for (int i = 0; i < 4; i++)
#pragma unroll
        for (int sp = 0; sp < 16; sp++) acc[i][sp] = 0ULL;

    float qc[4][DC], qn[4][DC];
    issue(0, 0);
    issue(1, 1);
    loadq(0, qc);

    for (int c = 0; c < NCH; ++c) {
        if (c + 1 < NCH) cp_wait1(); else cp_wait0();
        __syncthreads();
        if (c + 2 < NCH) issue(c + 2, (c + 2) % NBUF);
        if (c + 1 < NCH) loadq(c + 1, qn);

        const int buf = c % NBUF;
#pragma unroll
        for (int dd = 0; dd < DC; dd++) {
            u64 qv0 = pack2(qc[0][dd], qc[0][dd]);
            u64 qv1 = pack2(qc[1][dd], qc[1][dd]);
            u64 qv2 = pack2(qc[2][dd], qc[2][dd]);
            u64 qv3 = pack2(qc[3][dd], qc[3][dd]);
            const float* kb = &sk[SK(buf, dd, 0, lane)];
#pragma unroll
            for (int sp = 0; sp < 16; sp++) {
                u64 kv = pack2(kb[(2 * sp) * 32], kb[(2 * sp + 1) * 32]);
                acc[0][sp] = fma2_(qv0, kv, acc[0][sp]);
                acc[1][sp] = fma2_(qv1, kv, acc[1][sp]);
                acc[2][sp] = fma2_(qv2, kv, acc[2][sp]);
                acc[3][sp] = fma2_(qv3, kv, acc[3][sp]);
            }
        }
#pragma unroll
        for (int i = 0; i < 4; i++)
#pragma unroll
            for (int dd = 0; dd < DC; dd++) qc[i][dd] = qn[i][dd];
    }

    if (lv) {
#pragma unroll
        for (int i = 0; i < 4; i++) {
            float* ap = &g_part[dz][(((size_t)n * T_ + t0 + i) * T_) * L_ + l];
#pragma unroll
            for (int sp = 0; sp < 16; sp++) {
                float x, y;
                unpack2(acc[i][sp], x, y);
                ap[(2 * sp) * L_]     = x;
                ap[(2 * sp + 1) * L_] = y;
            }
        }
    }
}

// =====================================================================
// Reduce + softmax -> duplicated f32x2 attn table.
// =====================================================================
__global__ __launch_bounds__(256)
void reduce_softmax_kernel()
{
    const int idx = blockIdx.x * 256 + threadIdx.x;
    if (idx >= N_ * T_ * L_) return;
    const int l = idx % L_;
    const int t = (idx / L_) % T_;
    const int n = idx / (T_ * L_);

    const size_t base = (((size_t)n * T_ + t) * T_) * L_ + l;
    const float scale = 0.03608439182435161f;

    float v[32];
    float m = -1e30f;
#pragma unroll
    for (int s = 0; s < 32; s++) {
        v[s] = (g_part[0][base + s * L_] + g_part[1][base + s * L_]) * scale;
        m = fmaxf(m, v[s]);
    }
    float sum = 0.f;
#pragma unroll
    for (int s = 0; s < 32; s++) { float e = __expf(v[s] - m); v[s] = e; sum += e; }
    const float inv = 1.f / sum;
#pragma unroll
    for (int s = 0; s < 32; s++) {
        float a = v[s] * inv;
        g_a2[((size_t)n * 1024 + s * 32 + t) * L_ + l] = pack2(a, a);
    }
}

// =====================================================================
// Kernel B v5: out = sum_s a*kt + pek. t-split (halves LDS per fma2)
// + MLP-4 ring per column. Block 256 = 8 warps: (l-idx 0..3, t-half);
// lanes own TWO d-pair columns (d0+2lane, d0+64+2lane). Per s:
// 8 LDS.128 + 2 LDG.64 -> 32 fma2. No barriers in the mainloop.
// Grid (98, 16): x = 2*lblock + dz.
// =====================================================================
__global__ __launch_bounds__(256, 2)
void out_kernel(const float* __restrict__ pek, float* __restrict__ out)
{
    __shared__ u64 sa[4 * 1024];   // [l-idx][s*32+t]

    const int tid  = threadIdx.x;
    const int lane = tid & 31;
    const int w    = tid >> 5;            // 0..7
    const int li   = w & 3;
    const int th   = w >> 2;              // t-half
    const int l0   = (blockIdx.x >> 1) * 4;
    const int dz   = blockIdx.x & 1;
    const int n    = blockIdx.y;

    // prologue: a tile for 4 l's
#pragma unroll
    for (int i = 0; i < 16; i++) {
        int flat = i * 256 + tid;          // 0..4095
        int st = flat >> 2;
        int li2 = flat & 3;
        sa[li2 * 1024 + st] = g_a2[((size_t)n * 1024 + st) * L_ + l0 + li2];
    }
    __syncthreads();

    const int l = l0 + li;
    const u64* sa_w = sa + li * 1024 + th * 16;
    const float* ktb = g_kt + (((size_t)n * T_) * L_ + l) * D_;
    const int SSTRIDE = L_ * D_ / 2;       // u64 stride between s

    for (int dc = 0; dc < 3; dc++) {
        const int d0 = dz * DH + dc * 128 + 2 * lane;
        const u64* kp0 = reinterpret_cast<const u64*>(ktb + d0);
        const u64* kp1 = reinterpret_cast<const u64*>(ktb + d0 + 64);

        u64 oc[16][2];
#pragma unroll
        for (int t = 0; t < 16; t++) { oc[t][0] = 0ULL; oc[t][1] = 0ULL; }

        // MLP-8: two 4-deep prefetch rings
        u64 kvb0[4], kvb1[4];
#pragma unroll
        for (int j = 0; j < 4; j++) {
            kvb0[j] = __ldg(kp0 + (size_t)j * SSTRIDE);
            kvb1[j] = __ldg(kp1 + (size_t)j * SSTRIDE);
        }

#pragma unroll
        for (int s = 0; s < 32; s++) {
            u64 kv0 = kvb0[s & 3];
            u64 kv1 = kvb1[s & 3];
            if (s + 4 < 32) {
                kvb0[s & 3] = __ldg(kp0 + (size_t)(s + 4) * SSTRIDE);
                kvb1[s & 3] = __ldg(kp1 + (size_t)(s + 4) * SSTRIDE);
            }
            const ulonglong2* ap = reinterpret_cast<const ulonglong2*>(sa_w + s * 32);
#pragma unroll
            for (int tp = 0; tp < 8; tp++) {
                ulonglong2 a = ap[tp];
                oc[2 * tp][0]     = fma2_(a.x, kv0, oc[2 * tp][0]);
                oc[2 * tp][1]     = fma2_(a.x, kv1, oc[2 * tp][1]);
                oc[2 * tp + 1][0] = fma2_(a.y, kv0, oc[2 * tp + 1][0]);
                oc[2 * tp + 1][1] = fma2_(a.y, kv1, oc[2 * tp + 1][1]);
            }
        }

        const u64 pe0 = *reinterpret_cast<const u64*>(pek + (size_t)l * D_ + d0);
        const u64 pe1 = *reinterpret_cast<const u64*>(pek + (size_t)l * D_ + d0 + 64);
#pragma unroll
        for (int tt = 0; tt < 16; tt++) {
            const int t = th * 16 + tt;
            float* op = out + (((size_t)n * T_ + t) * L_ + l) * D_ + d0;
            *reinterpret_cast<u64*>(op)      = add2_(oc[tt][0], pe0);
            *reinterpret_cast<u64*>(op + 64) = add2_(oc[tt][1], pe1);
        }
    }
}

extern "C" void kernel_launch(void* const* d_in, const int* in_sizes, int n_in,
                              void* d_out, int out_size)
{
    const float* q   = (const float*)d_in[0];
    const float* k   = (const float*)d_in[1];
    const float* peq = (const float*)d_in[2];
    const float* pek = (const float*)d_in[3];
    float* out = (float*)d_out;

    transpose_kernel<<<dim3(6, 7, N_ * T_), 256>>>(k);
    scores_kernel<<<dim3(2 * NLB, N_, 2), 128>>>(q, k, peq);
    reduce_softmax_kernel<<<(N_ * T_ * L_ + 255) / 256, 256>>>();
    out_kernel<<<dim3(98, N_), 256>>>(pek, out);
}

// round 17
// speedup vs baseline: 1.6610x; 1.1230x over previous
#include <cuda_runtime.h>
#include <cstdint>

#define N_   16
#define T_   32
#define D_   768
#define DH   (D_ / 2)       // 384 per d-half
#define L_   196
#define NLB  7
#define DC   4
#define NCH  (DH / DC)      // 96 chunks per d-half (scores)
#define NBUF 3
#define SH   16             // s per scores CTA (s-split)

typedef unsigned long long u64;

// raw partial scores per d-half
__device__ float g_part[2][N_ * T_ * T_ * L_];
// transposed k: kt[n][s][l][d]
__device__ float g_kt[N_ * T_ * L_ * D_];
// softmaxed attn, duplicated f32x2: g_a2[n][s*32+t][l]
__device__ u64 g_a2[N_ * T_ * T_ * L_];

// ---- packed f32x2 helpers ----
__device__ __forceinline__ u64 pack2(float x, float y) {
    u64 r; asm("mov.b64 %0, {%1, %2};" : "=l"(r) : "f"(x), "f"(y)); return r;
}
__device__ __forceinline__ void unpack2(u64 v, float& x, float& y) {
    asm("mov.b64 {%0, %1}, %2;" : "=f"(x), "=f"(y) : "l"(v));
}
__device__ __forceinline__ u64 fma2_(u64 a, u64 b, u64 c) {
    u64 r; asm("fma.rn.f32x2 %0, %1, %2, %3;" : "=l"(r) : "l"(a), "l"(b), "l"(c)); return r;
}
__device__ __forceinline__ u64 add2_(u64 a, u64 b) {
    u64 r; asm("add.rn.f32x2 %0, %1, %2;" : "=l"(r) : "l"(a), "l"(b)); return r;
}

// ---- cp.async ----
__device__ __forceinline__ void cp16(uint32_t dst, const float* src) {
    asm volatile("cp.async.ca.shared.global [%0], [%1], 16;" :: "r"(dst), "l"(src));
}
__device__ __forceinline__ void cp_commit() { asm volatile("cp.async.commit_group;"); }
__device__ __forceinline__ void cp_wait1()  { asm volatile("cp.async.wait_group 1;"); }
__device__ __forceinline__ void cp_wait0()  { asm volatile("cp.async.wait_group 0;"); }

// scores k ring: [NBUF][DC][SH s][32 l] = 24 KB
#define SK(b, dd, s, l) ((((b) * DC + (dd)) * SH + (s)) * 32 + (l))

// =====================================================================
// Transpose (R13 exact): g_kt[n][s][l][d] = k[n][s][d][l].
// =====================================================================
__global__ __launch_bounds__(256)
void transpose_kernel(const float* __restrict__ k)
{
    __shared__ float tile[32][33];
    const int ns = blockIdx.z;
    const int l0 = blockIdx.y * 32;
    const int tid = threadIdx.x;
    const int c  = tid & 31;
    const int r0 = tid >> 5;
    const size_t base = (size_t)ns * D_ * L_;

    for (int j = 0; j < 4; j++) {
        const int d0 = (blockIdx.x * 4 + j) * 32;
#pragma unroll
        for (int rr = r0; rr < 32; rr += 8)
            tile[rr][c] = (l0 + c < L_) ? k[base + (size_t)(d0 + rr) * L_ + l0 + c] : 0.f;
        __syncthreads();
#pragma unroll
        for (int rr = r0; rr < 32; rr += 8)
            if (l0 + rr < L_)
                g_kt[base + (size_t)(l0 + rr) * D_ + d0 + c] = tile[c][rr];
        __syncthreads();
    }
}

// =====================================================================
// Kernel A: partial scores, d-half x t-half x s-half per CTA.
// Grid (28, 16, 2): x = 4*lblock + 2*tz + sz (sz-partners adjacent ->
// q L2 reuse; tz-partners distance 2 -> k L2 reuse), z = dz.
// Block 128, warp = 4 t's, lanes = l. acc halved (16 s) -> ~110 regs,
// 24 KB smem -> 4 CTAs/SM = 16 warps/SM.
// =====================================================================
__global__ __launch_bounds__(128, 4)
void scores_kernel(const float* __restrict__ q, const float* __restrict__ k,
                   const float* __restrict__ peq)
{
    __shared__ float sk[NBUF * DC * SH * 32];

    const int tid  = threadIdx.x;
    const int lane = tid & 31;
    const int tg   = tid >> 5;
    const int l0   = (blockIdx.x >> 2) * 32;
    const int tz   = (blockIdx.x >> 1) & 1;
    const int sz   = blockIdx.x & 1;
    const int n    = blockIdx.y;
    const int dz   = blockIdx.z;
    const int t0   = tz * 16 + tg * 4;
    const int s0   = sz * SH;
    const int l    = l0 + lane;
    const bool lv  = (l < L_);
    const int dbase = dz * DH;

    for (int i = tid; i < NBUF * DC * SH * 32; i += 128) sk[i] = 0.f;
    __syncthreads();

    const uint32_t sbase = (uint32_t)__cvta_generic_to_shared(sk);

    const int ll  = (tid & 7) * 4;
    const bool kv_ok = (l0 + ll < L_);
    // k base at this CTA's s-half
    const float* kb0 = k + (((size_t)n * T_ + s0) * D_ + dbase) * L_ + l0 + ll;

    auto issue = [&](int c, int buf) {
        const size_t cL = (size_t)(c * DC) * L_;
        if (kv_ok) {
            // DC*SH*8 = 512 float4 per chunk, 4 per thread
#pragma unroll
            for (int i = 0; i < 4; i++) {
                int r  = i * 16 + (tid >> 3);   // 0..63
                int s  = r & (SH - 1);          // 0..15
                int dd = r >> 4;                // 0..3
                cp16(sbase + (uint32_t)SK(buf, dd, s, ll) * 4,
                     kb0 + ((size_t)s * D_ + dd) * L_ + cL);
            }
        }
        cp_commit();
    };

    const float* qb0 = q + ((size_t)n * T_ * D_ + dbase) * L_ + l;
    const float* pb0 = peq + (size_t)l * D_ + dbase;

    auto loadq = [&](int c, float (&qr)[4][DC]) {
        if (lv) {
            float4 e = *reinterpret_cast<const float4*>(pb0 + c * DC);
            const size_t cL = (size_t)(c * DC) * L_;
#pragma unroll
            for (int i = 0; i < 4; i++) {
                qr[i][0] = __ldg(qb0 + ((size_t)(t0 + i) * D_ + 0) * L_ + cL) + e.x;
                qr[i][1] = __ldg(qb0 + ((size_t)(t0 + i) * D_ + 1) * L_ + cL) + e.y;
                qr[i][2] = __ldg(qb0 + ((size_t)(t0 + i) * D_ + 2) * L_ + cL) + e.z;
                qr[i][3] = __ldg(qb0 + ((size_t)(t0 + i) * D_ + 3) * L_ + cL) + e.w;
            }
        } else {
#pragma unroll
            for (int i = 0; i < 4; i++)
#pragma unroll
                for (int dd = 0; dd < DC; dd++) qr[i][dd] = 0.f;
        }
    };

    u64 acc[4][SH / 2];
#pragma unroll
    for (int i = 0; i < 4; i++)
#pragma unroll
        for (int sp = 0; sp < SH / 2; sp++) acc[i][sp] = 0ULL;

    float qc[4][DC], qn[4][DC];
    issue(0, 0);
    issue(1, 1);
    loadq(0, qc);

    for (int c = 0; c < NCH; ++c) {
        if (c + 1 < NCH) cp_wait1(); else cp_wait0();
        __syncthreads();
        if (c + 2 < NCH) issue(c + 2, (c + 2) % NBUF);
        if (c + 1 < NCH) loadq(c + 1, qn);

        const int buf = c % NBUF;
#pragma unroll
        for (int dd = 0; dd < DC; dd++) {
            u64 qv0 = pack2(qc[0][dd], qc[0][dd]);
            u64 qv1 = pack2(qc[1][dd], qc[1][dd]);
            u64 qv2 = pack2(qc[2][dd], qc[2][dd]);
            u64 qv3 = pack2(qc[3][dd], qc[3][dd]);
            const float* kb = &sk[SK(buf, dd, 0, lane)];
#pragma unroll
            for (int sp = 0; sp < SH / 2; sp++) {
                u64 kv = pack2(kb[(2 * sp) * 32], kb[(2 * sp + 1) * 32]);
                acc[0][sp] = fma2_(qv0, kv, acc[0][sp]);
                acc[1][sp] = fma2_(qv1, kv, acc[1][sp]);
                acc[2][sp] = fma2_(qv2, kv, acc[2][sp]);
                acc[3][sp] = fma2_(qv3, kv, acc[3][sp]);
            }
        }
#pragma unroll
        for (int i = 0; i < 4; i++)
#pragma unroll
            for (int dd = 0; dd < DC; dd++) qc[i][dd] = qn[i][dd];
    }

    if (lv) {
#pragma unroll
        for (int i = 0; i < 4; i++) {
            float* ap = &g_part[dz][(((size_t)n * T_ + t0 + i) * T_ + s0) * L_ + l];
#pragma unroll
            for (int sp = 0; sp < SH / 2; sp++) {
                float x, y;
                unpack2(acc[i][sp], x, y);
                ap[(2 * sp) * L_]     = x;
                ap[(2 * sp + 1) * L_] = y;
            }
        }
    }
}

// =====================================================================
// Reduce + softmax -> duplicated f32x2 attn table (R13 exact).
// =====================================================================
__global__ __launch_bounds__(256)
void reduce_softmax_kernel()
{
    const int idx = blockIdx.x * 256 + threadIdx.x;
    if (idx >= N_ * T_ * L_) return;
    const int l = idx % L_;
    const int t = (idx / L_) % T_;
    const int n = idx / (T_ * L_);

    const size_t base = (((size_t)n * T_ + t) * T_) * L_ + l;
    const float scale = 0.03608439182435161f;

    float v[32];
    float m = -1e30f;
#pragma unroll
    for (int s = 0; s < 32; s++) {
        v[s] = (g_part[0][base + s * L_] + g_part[1][base + s * L_]) * scale;
        m = fmaxf(m, v[s]);
    }
    float sum = 0.f;
#pragma unroll
    for (int s = 0; s < 32; s++) { float e = __expf(v[s] - m); v[s] = e; sum += e; }
    const float inv = 1.f / sum;
#pragma unroll
    for (int s = 0; s < 32; s++) {
        float a = v[s] * inv;
        g_a2[((size_t)n * 1024 + s * 32 + t) * L_ + l] = pack2(a, a);
    }
}

// =====================================================================
// Kernel B v4 (R13 exact): out = sum_s a*kt + pek, MLP-4 ring.
// Grid (98, 16): x = 2*lblock + dz. Block 128 = 4 warps, warp = l;
// lanes = d-pairs. No barriers in the mainloop.
// =====================================================================
__global__ __launch_bounds__(128, 4)
void out_kernel(const float* __restrict__ pek, float* __restrict__ out)
{
    __shared__ u64 sa[4 * 1024];   // [l-idx][s*32+t]

    const int tid  = threadIdx.x;
    const int lane = tid & 31;
    const int w    = tid >> 5;
    const int l0   = (blockIdx.x >> 1) * 4;   // 196 = 49*4
    const int dz   = blockIdx.x & 1;
    const int n    = blockIdx.y;

    // prologue: a tile for 4 l's
#pragma unroll
    for (int i = 0; i < 32; i++) {
        int flat = i * 128 + tid;
        int st = flat >> 2;
        int li = flat & 3;
        sa[li * 1024 + st] = g_a2[((size_t)n * 1024 + st) * L_ + l0 + li];
    }
    __syncthreads();

    const int l = l0 + w;
    const u64* sa_w = sa + w * 1024;
    const float* ktb = g_kt + (((size_t)n * T_) * L_ + l) * D_;
    const int SSTRIDE = L_ * D_ / 2;          // u64 stride between s

    for (int dc = 0; dc < 6; dc++) {
        const int d0 = dz * DH + dc * 64 + 2 * lane;
        const u64* kp = reinterpret_cast<const u64*>(ktb + d0);

        u64 oc[32];
#pragma unroll
        for (int t = 0; t < 32; t++) oc[t] = 0ULL;

        // 4-deep prefetch ring: 4 LDGs in flight per warp at all times
        u64 kvb[4];
#pragma unroll
        for (int j = 0; j < 4; j++) kvb[j] = __ldg(kp + (size_t)j * SSTRIDE);

#pragma unroll
        for (int s = 0; s < 32; s++) {
            u64 kvc = kvb[s & 3];
            if (s + 4 < 32) kvb[s & 3] = __ldg(kp + (size_t)(s + 4) * SSTRIDE);
            const ulonglong2* ap = reinterpret_cast<const ulonglong2*>(sa_w + s * 32);
#pragma unroll
            for (int tp = 0; tp < 16; tp++) {
                ulonglong2 a = ap[tp];
                oc[2 * tp]     = fma2_(a.x, kvc, oc[2 * tp]);
                oc[2 * tp + 1] = fma2_(a.y, kvc, oc[2 * tp + 1]);
            }
        }

        const u64 pe = *reinterpret_cast<const u64*>(pek + (size_t)l * D_ + d0);
#pragma unroll
        for (int t = 0; t < 32; t++) {
            *reinterpret_cast<u64*>(
                out + (((size_t)n * T_ + t) * L_ + l) * D_ + d0) = add2_(oc[t], pe);
        }
    }
}

extern "C" void kernel_launch(void* const* d_in, const int* in_sizes, int n_in,
                              void* d_out, int out_size)
{
    const float* q   = (const float*)d_in[0];
    const float* k   = (const float*)d_in[1];
    const float* peq = (const float*)d_in[2];
    const float* pek = (const float*)d_in[3];
    float* out = (float*)d_out;

    transpose_kernel<<<dim3(6, 7, N_ * T_), 256>>>(k);
    scores_kernel<<<dim3(4 * NLB, N_, 2), 128>>>(q, k, peq);
    reduce_softmax_kernel<<<(N_ * T_ * L_ + 255) / 256, 256>>>();
    out_kernel<<<dim3(98, N_), 128>>>(pek, out);
}